// round 2
// baseline (speedup 1.0000x reference)
#include <cuda_runtime.h>
#include <math.h>

#define BATCH 65536
#define SPB 4  // samples per block in kA (one warp each)

// -------- device scratch (allocation-free rule: __device__ globals) --------
__device__ float g_f [(size_t)BATCH * 420];   // DyConv output, flattened per sample
__device__ float g_hh[(size_t)BATCH * 256];   // relu(f@W1+b1)
__device__ float g_hr[(size_t)BATCH * 64];    // hh@W2 + f@Wres + b2 + bres

// ============================================================================
// Kernel A: fully fused per-sample pipeline up to f (one warp per sample)
// ============================================================================
__global__ __launch_bounds__(128) void kA(
    const float* __restrict__ x,
    const float* __restrict__ W_emb, const float* __restrict__ b_emb,
    const float* __restrict__ Wq, const float* __restrict__ bq,
    const float* __restrict__ Wk, const float* __restrict__ bk,
    const float* __restrict__ Wv, const float* __restrict__ bv,
    const float* __restrict__ Wo, const float* __restrict__ bo,
    const float* __restrict__ Wff1, const float* __restrict__ Wff2,
    const float* __restrict__ gnorm, const float* __restrict__ bnorm,
    const float* __restrict__ Wdy, const float* __restrict__ bdy,
    const float* __restrict__ channels)
{
    __shared__ float sWe[588], sbe[14];
    __shared__ float sWq[112], sWk[112], sWv[112];
    __shared__ float sbq[8], sbk[8], sbv[8];
    __shared__ float sWo[112], sbo[14];
    __shared__ float sF1[700], sF2[700];
    __shared__ float sg[14], sb[14];
    __shared__ float sWdy[900], sbdy[30];
    __shared__ float sAdj[196];
    __shared__ float bA[SPB][420];   // xe / rowbuf / x3
    __shared__ float bB[SPB][420];   // raw x / q / agg / x(decomp1)
    __shared__ float bC[SPB][420];   // k / x1 / x2 / dyconv h
    __shared__ float bV[SPB][240];   // v
    __shared__ float smv[SPB][30];
    __shared__ float swt[SPB][4];
    __shared__ int   sdl[SPB][4];

    const int tid = threadIdx.x;
    for (int i = tid; i < 588; i += 128) sWe[i] = W_emb[i];
    for (int i = tid; i < 112; i += 128) { sWq[i]=Wq[i]; sWk[i]=Wk[i]; sWv[i]=Wv[i]; sWo[i]=Wo[i]; }
    for (int i = tid; i < 700; i += 128) { sF1[i]=Wff1[i]; sF2[i]=Wff2[i]; }
    for (int i = tid; i < 900; i += 128) sWdy[i] = Wdy[i];
    if (tid < 30) sbdy[tid] = bdy[tid];
    if (tid < 14) { sbe[tid]=b_emb[tid]; sbo[tid]=bo[tid]; sg[tid]=gnorm[tid]; sb[tid]=bnorm[tid]; }
    if (tid < 8)  { sbq[tid]=bq[tid]; sbk[tid]=bk[tid]; sbv[tid]=bv[tid]; }
    if (tid < 14) {
        const float* row = channels + tid * 14;
        float mx = -1e30f;
        #pragma unroll
        for (int j = 0; j < 14; j++) mx = fmaxf(mx, row[j]);
        float s = 0.f;
        #pragma unroll
        for (int j = 0; j < 14; j++) s += expf(row[j] - mx);
        float inv = 1.f / s;
        #pragma unroll
        for (int j = 0; j < 14; j++) sAdj[tid * 14 + j] = expf(row[j] - mx) * inv;
    }
    __syncthreads();

    const int w = tid >> 5, lane = tid & 31;
    const int smp = blockIdx.x * SPB + w;
    float* A = bA[w]; float* Bq = bB[w]; float* C = bC[w]; float* V = bV[w];
    const float* xin = x + (size_t)smp * 420;

    // ---- load raw x ----
    for (int i = lane; i < 420; i += 32) Bq[i] = xin[i];
    __syncwarp();

    // ---- Conv1d embed (cross-correlation, zero pad) : A[t*14+o] ----
    for (int idx = lane; idx < 420; idx += 32) {
        int t = idx / 14, o = idx - t * 14;
        int base = t * 14;
        float acc = sbe[o];
        const float* wr = &sWe[o * 42];
        #pragma unroll
        for (int ci = 0; ci < 14; ci++) {
            float x0 = Bq[base + ci];
            float xm = (t > 0)  ? Bq[base - 14 + ci] : 0.f;
            float xp = (t < 29) ? Bq[base + 14 + ci] : 0.f;
            acc += wr[ci*3] * xm + wr[ci*3+1] * x0 + wr[ci*3+2] * xp;
        }
        A[idx] = acc;
    }
    __syncwarp();

    // ---- QKV (h-major: [h*30+t]) : q->Bq, k->C, v->V ----
    for (int idx = lane; idx < 240; idx += 32) {
        int h = idx / 30, t = idx - h * 30;
        float aq = sbq[h], ak = sbk[h], av = sbv[h];
        const float* xr = &A[t * 14];
        #pragma unroll
        for (int d = 0; d < 14; d++) {
            float xv = xr[d];
            aq += xv * sWq[d*8+h];
            ak += xv * sWk[d*8+h];
            av += xv * sWv[d*8+h];
        }
        Bq[idx] = aq; C[idx] = ak; V[idx] = av;
    }
    __syncwarp();

    // ---- circular correlation corr[tau] = sum_t q[t]*k[(t - tau) mod L],
    //      mean over 8 heads : smv[tau]
    //      (irfft(Q * conj(K))[tau] -- NOTE the MINUS tau; round-1 had +tau) ----
    if (lane < 30) {
        float acc = 0.f;
        #pragma unroll
        for (int h = 0; h < 8; h++) {
            const float* q = &Bq[h * 30];
            const float* k = &C[h * 30];
            int t2 = (lane == 0) ? 0 : (30 - lane);   // (0 - tau) mod 30
            #pragma unroll
            for (int t = 0; t < 30; t++) {
                acc += q[t] * k[t2];
                t2++; if (t2 == 30) t2 = 0;
            }
        }
        smv[w][lane] = acc * 0.125f;
    }
    __syncwarp();

    // ---- top-3 (strict >, first-index tie-break = lax.top_k) + softmax ----
    if (lane == 0) {
        float wv[3]; int dl[3];
        for (int p = 0; p < 3; p++) {
            float best = -1e30f; int bi = 0;
            for (int i = 0; i < 30; i++) {
                float v = smv[w][i];
                if (v > best) { best = v; bi = i; }
            }
            wv[p] = best; dl[p] = bi; smv[w][bi] = -1e30f;
        }
        float e0 = 1.f;
        float e1 = expf(wv[1] - wv[0]);
        float e2 = expf(wv[2] - wv[0]);
        float inv = 1.f / (e0 + e1 + e2);
        swt[w][0] = e0*inv; swt[w][1] = e1*inv; swt[w][2] = e2*inv;
        sdl[w][0] = dl[0];  sdl[w][1] = dl[1];  sdl[w][2] = dl[2];
    }
    __syncwarp();

    // ---- delay aggregate : agg -> Bq (q dead) ----
    {
        float w0 = swt[w][0], w1 = swt[w][1], w2 = swt[w][2];
        int d0 = sdl[w][0], d1 = sdl[w][1], d2 = sdl[w][2];
        for (int idx = lane; idx < 240; idx += 32) {
            int h = idx / 30, t = idx - h * 30;
            int i0 = t + d0; if (i0 >= 30) i0 -= 30;
            int i1 = t + d1; if (i1 >= 30) i1 -= 30;
            int i2 = t + d2; if (i2 >= 30) i2 -= 30;
            const float* vh = &V[h * 30];
            Bq[idx] = w0 * vh[i0] + w1 * vh[i1] + w2 * vh[i2];
        }
    }
    __syncwarp();

    // ---- x1 = xe + agg@Wo + bo -> C (k dead) ----
    for (int idx = lane; idx < 420; idx += 32) {
        int t = idx / 14, d = idx - t * 14;
        float acc = A[idx] + sbo[d];
        #pragma unroll
        for (int h = 0; h < 8; h++) acc += Bq[h*30 + t] * sWo[h*14 + d];
        C[idx] = acc;
    }
    __syncwarp();

    // ---- series_decomp 1 (replicate-pad MA-25) : Bq = C - mean ----
    for (int idx = lane; idx < 420; idx += 32) {
        int t = idx / 14, d = idx - t * 14;
        float m = 0.f;
        #pragma unroll
        for (int j = -12; j <= 12; j++) {
            int jt = t + j; jt = jt < 0 ? 0 : (jt > 29 ? 29 : jt);
            m += C[jt * 14 + d];
        }
        Bq[idx] = C[idx] - m * (1.f / 25.f);
    }
    __syncwarp();

    // ---- FFN (exact GELU), 2 rows/iter, rowbuf in A : C = Bq + y ----
    for (int t0 = 0; t0 < 30; t0 += 2) {
        for (int idx = lane; idx < 100; idx += 32) {
            int r = idx / 50, fi = idx - r * 50;
            const float* xr = &Bq[(t0 + r) * 14];
            float acc = 0.f;
            #pragma unroll
            for (int d = 0; d < 14; d++) acc += xr[d] * sF1[d*50 + fi];
            A[idx] = 0.5f * acc * (1.f + erff(acc * 0.70710678118654752f));
        }
        __syncwarp();
        for (int idx = lane; idx < 28; idx += 32) {
            int r = idx / 14, d = idx - r * 14;
            const float* yb = &A[r * 50];
            float acc = 0.f;
            #pragma unroll
            for (int f = 0; f < 50; f++) acc += yb[f] * sF2[f*14 + d];
            C[(t0 + r)*14 + d] = Bq[(t0 + r)*14 + d] + acc;
        }
        __syncwarp();
    }

    // ---- series_decomp 2 : A = C - mean ----
    for (int idx = lane; idx < 420; idx += 32) {
        int t = idx / 14, d = idx - t * 14;
        float m = 0.f;
        #pragma unroll
        for (int j = -12; j <= 12; j++) {
            int jt = t + j; jt = jt < 0 ? 0 : (jt > 29 ? 29 : jt);
            m += C[jt * 14 + d];
        }
        A[idx] = C[idx] - m * (1.f / 25.f);
    }
    __syncwarp();

    // ---- layernorm rows (D=14) in place ----
    if (lane < 30) {
        float* r = &A[lane * 14];
        float m = 0.f;
        #pragma unroll
        for (int d = 0; d < 14; d++) m += r[d];
        m *= (1.f / 14.f);
        float v = 0.f;
        #pragma unroll
        for (int d = 0; d < 14; d++) { float dd = r[d] - m; v += dd * dd; }
        v *= (1.f / 14.f);
        float inv = rsqrtf(v + 1e-5f);
        #pragma unroll
        for (int d = 0; d < 14; d++) r[d] = (r[d] - m) * inv * sg[d] + sb[d];
    }
    __syncwarp();

    // ---- DyConv h[d][l] = sum_m x[m][d]*Wdy[m][l] + bdy[l] -> C ----
    for (int idx = lane; idx < 420; idx += 32) {
        int dch = idx / 30, l = idx - dch * 30;
        float acc = sbdy[l];
        #pragma unroll
        for (int m = 0; m < 30; m++) acc += A[m*14 + dch] * sWdy[m*30 + l];
        C[idx] = acc;
    }
    __syncwarp();

    // ---- dy = relu(adj @ h) -> f (global) ----
    float* fo = g_f + (size_t)smp * 420;
    for (int idx = lane; idx < 420; idx += 32) {
        int i = idx / 30, l = idx - i * 30;
        float acc = 0.f;
        #pragma unroll
        for (int j = 0; j < 14; j++) acc += sAdj[i*14 + j] * C[j*30 + l];
        fo[idx] = fmaxf(acc, 0.f);
    }
}

// ============================================================================
// Kernel B: hh = relu(f @ W1 + b1)   M=65536, K=420, N=256
// BM=64, BN=256 (full N -> f read exactly once), BK=28, 256 threads, 8x8/thread
// ============================================================================
__global__ __launch_bounds__(256) void kB(const float* __restrict__ W1,
                                          const float* __restrict__ b1)
{
    __shared__ float As[64][29];
    __shared__ __align__(16) float Bs[28][256];
    const int tid = threadIdx.x;
    const int m0 = (tid >> 5) * 8;   // 8 thread rows
    const int n0 = (tid & 31) * 8;   // 32 thread cols
    const size_t mbase = (size_t)blockIdx.x * 64;
    float acc[8][8] = {};

    for (int k0 = 0; k0 < 420; k0 += 28) {
        for (int idx = tid; idx < 64 * 28; idx += 256) {
            int m = idx / 28, kk = idx - m * 28;
            As[m][kk] = g_f[(mbase + m) * 420 + k0 + kk];
        }
        for (int idx = tid; idx < 28 * 64; idx += 256) {   // 64 float4 per row
            int r = idx / 64, c4 = idx - r * 64;
            reinterpret_cast<float4*>(Bs[r])[c4] =
                reinterpret_cast<const float4*>(W1 + (size_t)(k0 + r) * 256)[c4];
        }
        __syncthreads();
        #pragma unroll
        for (int kk = 0; kk < 28; kk++) {
            float a[8];
            #pragma unroll
            for (int i = 0; i < 8; i++) a[i] = As[m0 + i][kk];
            float4 bv0 = reinterpret_cast<const float4*>(&Bs[kk][n0])[0];
            float4 bv1 = reinterpret_cast<const float4*>(&Bs[kk][n0])[1];
            float b[8] = {bv0.x, bv0.y, bv0.z, bv0.w, bv1.x, bv1.y, bv1.z, bv1.w};
            #pragma unroll
            for (int i = 0; i < 8; i++)
                #pragma unroll
                for (int j = 0; j < 8; j++) acc[i][j] += a[i] * b[j];
        }
        __syncthreads();
    }
    float bb[8];
    #pragma unroll
    for (int j = 0; j < 8; j++) bb[j] = b1[n0 + j];
    #pragma unroll
    for (int i = 0; i < 8; i++) {
        float* o = g_hh + (mbase + m0 + i) * 256 + n0;
        #pragma unroll
        for (int j = 0; j < 8; j++) o[j] = fmaxf(acc[i][j] + bb[j], 0.f);
    }
}

// ============================================================================
// Kernel C: hr = [hh | f] @ [W2 ; Wres] + b2 + bres    M=65536, K=676, N=64
// BM=128, BN=64, BK=26, 256 threads, 8x4/thread
// ============================================================================
__global__ __launch_bounds__(256) void kC(const float* __restrict__ W2,
                                          const float* __restrict__ b2,
                                          const float* __restrict__ Wres,
                                          const float* __restrict__ bres)
{
    __shared__ float As[128][27];
    __shared__ __align__(16) float Bs[26][64];
    const int tid = threadIdx.x;
    const int m0 = (tid >> 4) * 8;   // 16 thread rows
    const int n0 = (tid & 15) * 4;   // 16 thread cols
    const size_t mbase = (size_t)blockIdx.x * 128;
    float acc[8][4] = {};

    for (int k0 = 0; k0 < 676; k0 += 26) {
        for (int idx = tid; idx < 128 * 26; idx += 256) {
            int m = idx / 26, kk = idx - m * 26;
            int k = k0 + kk;
            As[m][kk] = (k < 256) ? g_hh[(mbase + m) * 256 + k]
                                  : g_f [(mbase + m) * 420 + (k - 256)];
        }
        for (int idx = tid; idx < 26 * 64; idx += 256) {
            int r = idx / 64, c = idx - r * 64;
            int k = k0 + r;
            Bs[r][c] = (k < 256) ? W2[(size_t)k * 64 + c]
                                 : Wres[(size_t)(k - 256) * 64 + c];
        }
        __syncthreads();
        #pragma unroll
        for (int kk = 0; kk < 26; kk++) {
            float a[8];
            #pragma unroll
            for (int i = 0; i < 8; i++) a[i] = As[m0 + i][kk];
            float4 b4 = *reinterpret_cast<const float4*>(&Bs[kk][n0]);
            float b[4] = {b4.x, b4.y, b4.z, b4.w};
            #pragma unroll
            for (int i = 0; i < 8; i++)
                #pragma unroll
                for (int j = 0; j < 4; j++) acc[i][j] += a[i] * b[j];
        }
        __syncthreads();
    }
    float bb[4];
    #pragma unroll
    for (int j = 0; j < 4; j++) bb[j] = b2[n0 + j] + bres[n0 + j];
    #pragma unroll
    for (int i = 0; i < 8; i++) {
        float* o = g_hr + (mbase + m0 + i) * 64 + n0;
        #pragma unroll
        for (int j = 0; j < 4; j++) o[j] = acc[i][j] + bb[j];
    }
}

// ============================================================================
// Kernel D: out = LN64(hr) @ W3 + b3   (one warp per sample)
// ============================================================================
__global__ __launch_bounds__(256) void kD(const float* __restrict__ g_ln,
                                          const float* __restrict__ b_ln,
                                          const float* __restrict__ W3,
                                          const float* __restrict__ b3,
                                          float* __restrict__ out)
{
    int w = threadIdx.x >> 5, lane = threadIdx.x & 31;
    size_t s = (size_t)blockIdx.x * 8 + w;
    const float* r = g_hr + s * 64;
    float v0 = r[lane], v1 = r[lane + 32];
    float sum = v0 + v1, sq = v0 * v0 + v1 * v1;
    #pragma unroll
    for (int o = 16; o; o >>= 1) {
        sum += __shfl_xor_sync(0xffffffffu, sum, o);
        sq  += __shfl_xor_sync(0xffffffffu, sq,  o);
    }
    float m = sum * (1.f / 64.f);
    float var = sq * (1.f / 64.f) - m * m;
    float inv = rsqrtf(var + 1e-5f);
    float y0 = (v0 - m) * inv * g_ln[lane]      + b_ln[lane];
    float y1 = (v1 - m) * inv * g_ln[lane + 32] + b_ln[lane + 32];
    float d = y0 * W3[lane] + y1 * W3[lane + 32];
    #pragma unroll
    for (int o = 16; o; o >>= 1) d += __shfl_xor_sync(0xffffffffu, d, o);
    if (lane == 0) out[s] = d + b3[0];
}

// ============================================================================
extern "C" void kernel_launch(void* const* d_in, const int* in_sizes, int n_in,
                              void* d_out, int out_size)
{
    (void)in_sizes; (void)n_in; (void)out_size;
    const float* x = (const float*)d_in[0];

    kA<<<BATCH / SPB, 128>>>(x,
        (const float*)d_in[1],  (const float*)d_in[2],
        (const float*)d_in[3],  (const float*)d_in[4],
        (const float*)d_in[5],  (const float*)d_in[6],
        (const float*)d_in[7],  (const float*)d_in[8],
        (const float*)d_in[9],  (const float*)d_in[10],
        (const float*)d_in[11], (const float*)d_in[12],
        (const float*)d_in[13], (const float*)d_in[14],
        (const float*)d_in[15], (const float*)d_in[16],
        (const float*)d_in[17]);

    kB<<<BATCH / 64, 256>>>((const float*)d_in[18], (const float*)d_in[19]);

    kC<<<BATCH / 128, 256>>>((const float*)d_in[20], (const float*)d_in[21],
                             (const float*)d_in[22], (const float*)d_in[23]);

    kD<<<BATCH / 8, 256>>>((const float*)d_in[24], (const float*)d_in[25],
                           (const float*)d_in[26], (const float*)d_in[27],
                           (float*)d_out);
}

// round 3
// speedup vs baseline: 1.5918x; 1.5918x over previous
#include <cuda_runtime.h>
#include <math.h>

#define BATCH 65536
#define FULL 0xffffffffu

// -------- device scratch (allocation-free rule: __device__ globals) --------
__device__ float g_f [(size_t)BATCH * 420];   // DyConv output, flattened per sample
__device__ float g_hh[(size_t)BATCH * 256];   // relu(f@W1+b1)
__device__ float g_hr[(size_t)BATCH * 64];    // hh@W2 + f@Wres + b2 + bres

// ============================================================================
// Kernel A: register-resident per-sample pipeline. 1 warp = 1 sample,
// lane t in [0,30) holds the 14-channel row of time step t in registers.
// Weights live in shared with warp-uniform (broadcast) access.
// ============================================================================
__global__ __launch_bounds__(256) void kA(
    const float* __restrict__ x,
    const float* __restrict__ W_emb, const float* __restrict__ b_emb,
    const float* __restrict__ Wq, const float* __restrict__ bq,
    const float* __restrict__ Wk, const float* __restrict__ bk,
    const float* __restrict__ Wv, const float* __restrict__ bv,
    const float* __restrict__ Wo, const float* __restrict__ bo,
    const float* __restrict__ Wff1, const float* __restrict__ Wff2,
    const float* __restrict__ gnorm, const float* __restrict__ bnorm,
    const float* __restrict__ Wdy, const float* __restrict__ bdy,
    const float* __restrict__ channels)
{
    // ---- block-shared weights ----
    __shared__ float sWe[588], sbe[14];
    __shared__ float sWq[112], sWk[112], sWv[112];
    __shared__ float sbq[8], sbk[8], sbv[8];
    __shared__ float sWo[112], sbo[14];
    __shared__ float sF1[700], sF2[700];
    __shared__ float sg[14], sb[14];
    __shared__ float sWdy[900], sbdy[30];
    __shared__ float sAdj[196];
    // ---- per-warp scratch: qs[8][32] | ks[8][32]; x3 rows reuse qs area ----
    __shared__ float scr[8][512];
    __shared__ float smv[8][32];
    __shared__ float swt[8][4];
    __shared__ int   sdl[8][4];

    const int tid = threadIdx.x;
    for (int i = tid; i < 588; i += 256) sWe[i] = W_emb[i];
    for (int i = tid; i < 112; i += 256) { sWq[i]=Wq[i]; sWk[i]=Wk[i]; sWv[i]=Wv[i]; sWo[i]=Wo[i]; }
    for (int i = tid; i < 700; i += 256) { sF1[i]=Wff1[i]; sF2[i]=Wff2[i]; }
    for (int i = tid; i < 900; i += 256) sWdy[i] = Wdy[i];
    if (tid < 30) sbdy[tid] = bdy[tid];
    if (tid < 14) { sbe[tid]=b_emb[tid]; sbo[tid]=bo[tid]; sg[tid]=gnorm[tid]; sb[tid]=bnorm[tid]; }
    if (tid < 8)  { sbq[tid]=bq[tid]; sbk[tid]=bk[tid]; sbv[tid]=bv[tid]; }
    if (tid < 14) {
        const float* row = channels + tid * 14;
        float mx = -1e30f;
        #pragma unroll
        for (int j = 0; j < 14; j++) mx = fmaxf(mx, row[j]);
        float s = 0.f;
        #pragma unroll
        for (int j = 0; j < 14; j++) s += expf(row[j] - mx);
        float inv = 1.f / s;
        #pragma unroll
        for (int j = 0; j < 14; j++) sAdj[tid * 14 + j] = expf(row[j] - mx) * inv;
    }
    __syncthreads();

    const int w    = tid >> 5;
    const int lane = tid & 31;
    const int t    = (lane < 30) ? lane : 0;     // clamped time index
    const bool act = (lane < 30);
    const int smp  = blockIdx.x * 8 + w;
    float* qs = &scr[w][0];     // [h*32 + t]
    float* ks = &scr[w][256];   // [h*32 + t]
    float* x3s = &scr[w][0];    // reused after correlation (420 <= 512)

    // ---- load row x[t][0..13] ----
    float xr[14];
    {
        const float* p = x + (size_t)smp * 420 + t * 14;
        #pragma unroll
        for (int d = 0; d < 14; d++) xr[d] = p[d];
    }

    // ---- Conv1d embed (kernel 3, zero pad) via shuffles ----
    float xe[14];
    {
        float xm[14], xp[14];
        #pragma unroll
        for (int d = 0; d < 14; d++) {
            float up = __shfl_up_sync(FULL, xr[d], 1);
            float dn = __shfl_down_sync(FULL, xr[d], 1);
            xm[d] = (lane > 0)  ? up : 0.f;
            xp[d] = (lane < 29) ? dn : 0.f;
        }
        #pragma unroll
        for (int o = 0; o < 14; o++) {
            float acc = sbe[o];
            #pragma unroll
            for (int ci = 0; ci < 14; ci++) {
                acc += sWe[o*42 + ci*3 + 0] * xm[ci];
                acc += sWe[o*42 + ci*3 + 1] * xr[ci];
                acc += sWe[o*42 + ci*3 + 2] * xp[ci];
            }
            xe[o] = acc;
        }
    }

    // ---- QKV per lane (head-major, E=1) ----
    float q[8], k[8], v[8];
    #pragma unroll
    for (int h = 0; h < 8; h++) { q[h]=sbq[h]; k[h]=sbk[h]; v[h]=sbv[h]; }
    #pragma unroll
    for (int d = 0; d < 14; d++) {
        float xv = xe[d];
        #pragma unroll
        for (int h = 0; h < 8; h++) {
            q[h] += xv * sWq[d*8+h];
            k[h] += xv * sWk[d*8+h];
            v[h] += xv * sWv[d*8+h];
        }
    }
    if (act) {
        #pragma unroll
        for (int h = 0; h < 8; h++) { qs[h*32 + t] = q[h]; ks[h*32 + t] = k[h]; }
    }
    __syncwarp();

    // ---- circular correlation: corr[tau] = sum_{t,h} q[t][h] * k[(t-tau) mod 30][h]
    //      lane = tau; mean over heads ----
    {
        float acc = 0.f;
        #pragma unroll
        for (int tq = 0; tq < 30; tq++) {
            int src = tq - t; if (src < 0) src += 30;
            #pragma unroll
            for (int h = 0; h < 8; h++)
                acc += qs[h*32 + tq] * ks[h*32 + src];
        }
        if (act) smv[w][t] = acc * 0.125f;
    }
    __syncwarp();

    // ---- top-3 (strict >, first-index tie-break) + softmax (lane 0 serial) ----
    if (lane == 0) {
        float wv[3]; int dl[3];
        float buf[30];
        #pragma unroll
        for (int i = 0; i < 30; i++) buf[i] = smv[w][i];
        for (int p = 0; p < 3; p++) {
            float best = -1e30f; int bi = 0;
            #pragma unroll
            for (int i = 0; i < 30; i++) {
                if (buf[i] > best) { best = buf[i]; bi = i; }
            }
            wv[p] = best; dl[p] = bi; buf[bi] = -1e30f;
        }
        float e1 = expf(wv[1] - wv[0]);
        float e2 = expf(wv[2] - wv[0]);
        float inv = 1.f / (1.f + e1 + e2);
        swt[w][0] = inv; swt[w][1] = e1*inv; swt[w][2] = e2*inv;
        sdl[w][0] = dl[0]; sdl[w][1] = dl[1]; sdl[w][2] = dl[2];
    }
    __syncwarp();

    // ---- delay aggregation: agg[t][h] = sum_k w_k * v[(t+d_k) mod 30][h] ----
    float agg[8];
    {
        float w0 = swt[w][0], w1 = swt[w][1], w2 = swt[w][2];
        int d0 = sdl[w][0], d1 = sdl[w][1], d2 = sdl[w][2];
        int s0 = t + d0; if (s0 >= 30) s0 -= 30;
        int s1 = t + d1; if (s1 >= 30) s1 -= 30;
        int s2 = t + d2; if (s2 >= 30) s2 -= 30;
        #pragma unroll
        for (int h = 0; h < 8; h++) {
            float a = w0 * __shfl_sync(FULL, v[h], s0);
            a      += w1 * __shfl_sync(FULL, v[h], s1);
            a      += w2 * __shfl_sync(FULL, v[h], s2);
            agg[h] = a;
        }
    }

    // ---- x1 = xe + agg @ Wo + bo ----
    float x1[14];
    #pragma unroll
    for (int d = 0; d < 14; d++) {
        float a = xe[d] + sbo[d];
        #pragma unroll
        for (int h = 0; h < 8; h++) a += agg[h] * sWo[h*14 + d];
        x1[d] = a;
    }

    // ---- series_decomp 1 via shuffle cumsum (replicate-pad MA-25) ----
    float xd[14];
    {
        const float fc0  = (t < 12) ? (float)(12 - t) : 0.f;
        const float fc29 = (t > 17) ? (float)(t - 17) : 0.f;
        const int hi   = (t + 12 > 29) ? 29 : t + 12;
        const int lom1 = t - 13;
        const int loix = (lom1 < 0) ? 0 : lom1;
        #pragma unroll
        for (int d = 0; d < 14; d++) {
            float val = x1[d];
            float cs = val;
            #pragma unroll
            for (int off = 1; off < 32; off <<= 1) {
                float o = __shfl_up_sync(FULL, cs, off);
                if (lane >= off) cs += o;
            }
            float cshi = __shfl_sync(FULL, cs, hi);
            float cslo = __shfl_sync(FULL, cs, loix);
            float ssum = cshi - ((lom1 >= 0) ? cslo : 0.f);
            float x0  = __shfl_sync(FULL, val, 0);
            float x29 = __shfl_sync(FULL, val, 29);
            float mean = (ssum + fc0 * x0 + fc29 * x29) * (1.f / 25.f);
            xd[d] = x1[d] - mean;
        }
    }

    // ---- FFN: y = gelu_exact(xd @ F1) @ F2 ; x2 = xd + y ----
    float x2[14];
    {
        float y[14];
        #pragma unroll
        for (int d = 0; d < 14; d++) y[d] = 0.f;
        #pragma unroll 5
        for (int f = 0; f < 50; f++) {
            float hs = xd[0] * sF1[f];
            #pragma unroll
            for (int d = 1; d < 14; d++) hs += xd[d] * sF1[d*50 + f];
            float g = 0.5f * hs * (1.f + erff(hs * 0.70710678118654752f));
            #pragma unroll
            for (int d = 0; d < 14; d++) y[d] += g * sF2[f*14 + d];
        }
        #pragma unroll
        for (int d = 0; d < 14; d++) x2[d] = xd[d] + y[d];
    }

    // ---- series_decomp 2 ----
    float x3[14];
    {
        const float fc0  = (t < 12) ? (float)(12 - t) : 0.f;
        const float fc29 = (t > 17) ? (float)(t - 17) : 0.f;
        const int hi   = (t + 12 > 29) ? 29 : t + 12;
        const int lom1 = t - 13;
        const int loix = (lom1 < 0) ? 0 : lom1;
        #pragma unroll
        for (int d = 0; d < 14; d++) {
            float val = x2[d];
            float cs = val;
            #pragma unroll
            for (int off = 1; off < 32; off <<= 1) {
                float o = __shfl_up_sync(FULL, cs, off);
                if (lane >= off) cs += o;
            }
            float cshi = __shfl_sync(FULL, cs, hi);
            float cslo = __shfl_sync(FULL, cs, loix);
            float ssum = cshi - ((lom1 >= 0) ? cslo : 0.f);
            float x0  = __shfl_sync(FULL, val, 0);
            float x29 = __shfl_sync(FULL, val, 29);
            float mean = (ssum + fc0 * x0 + fc29 * x29) * (1.f / 25.f);
            x3[d] = x2[d] - mean;
        }
    }

    // ---- layernorm over 14 channels (per lane) ----
    {
        float m = 0.f;
        #pragma unroll
        for (int d = 0; d < 14; d++) m += x3[d];
        m *= (1.f / 14.f);
        float var = 0.f;
        #pragma unroll
        for (int d = 0; d < 14; d++) { float dd = x3[d] - m; var += dd * dd; }
        var *= (1.f / 14.f);
        float inv = rsqrtf(var + 1e-5f);
        #pragma unroll
        for (int d = 0; d < 14; d++) x3[d] = (x3[d] - m) * inv * sg[d] + sb[d];
    }

    // ---- DyConv: h2[d][l] = sum_m x3[m][d] * Wdy[m][l] + bdy[l]  (lane = l) ----
    __syncwarp();            // all corr reads of qs/ks long done; reuse as x3s
    if (act) {
        #pragma unroll
        for (int d = 0; d < 14; d++) x3s[t*14 + d] = x3[d];
    }
    __syncwarp();
    float accd[14];
    {
        float wdy[30];
        #pragma unroll
        for (int m = 0; m < 30; m++) wdy[m] = sWdy[m*30 + t];
        #pragma unroll
        for (int d = 0; d < 14; d++) accd[d] = sbdy[t];
        #pragma unroll
        for (int m = 0; m < 30; m++) {
            float wm = wdy[m];
            #pragma unroll
            for (int d = 0; d < 14; d++) accd[d] += x3s[m*14 + d] * wm;
        }
    }

    // ---- dy = relu(adj @ h2) -> g_f ----
    {
        float* fo = g_f + (size_t)smp * 420;
        #pragma unroll
        for (int i = 0; i < 14; i++) {
            float a = 0.f;
            #pragma unroll
            for (int j = 0; j < 14; j++) a += sAdj[i*14 + j] * accd[j];
            if (act) fo[i*30 + t] = fmaxf(a, 0.f);
        }
    }
}

// ============================================================================
// Kernel B: hh = relu(f @ W1 + b1)   M=65536, K=420, N=256
// ============================================================================
__global__ __launch_bounds__(256) void kB(const float* __restrict__ W1,
                                          const float* __restrict__ b1)
{
    __shared__ float As[64][29];
    __shared__ __align__(16) float Bs[28][256];
    const int tid = threadIdx.x;
    const int m0 = (tid >> 5) * 8;
    const int n0 = (tid & 31) * 8;
    const size_t mbase = (size_t)blockIdx.x * 64;
    float acc[8][8] = {};

    for (int k0 = 0; k0 < 420; k0 += 28) {
        for (int idx = tid; idx < 64 * 28; idx += 256) {
            int m = idx / 28, kk = idx - m * 28;
            As[m][kk] = g_f[(mbase + m) * 420 + k0 + kk];
        }
        for (int idx = tid; idx < 28 * 64; idx += 256) {
            int r = idx / 64, c4 = idx - r * 64;
            reinterpret_cast<float4*>(Bs[r])[c4] =
                reinterpret_cast<const float4*>(W1 + (size_t)(k0 + r) * 256)[c4];
        }
        __syncthreads();
        #pragma unroll
        for (int kk = 0; kk < 28; kk++) {
            float a[8];
            #pragma unroll
            for (int i = 0; i < 8; i++) a[i] = As[m0 + i][kk];
            float4 bv0 = reinterpret_cast<const float4*>(&Bs[kk][n0])[0];
            float4 bv1 = reinterpret_cast<const float4*>(&Bs[kk][n0])[1];
            float b[8] = {bv0.x, bv0.y, bv0.z, bv0.w, bv1.x, bv1.y, bv1.z, bv1.w};
            #pragma unroll
            for (int i = 0; i < 8; i++)
                #pragma unroll
                for (int j = 0; j < 8; j++) acc[i][j] += a[i] * b[j];
        }
        __syncthreads();
    }
    float bb[8];
    #pragma unroll
    for (int j = 0; j < 8; j++) bb[j] = b1[n0 + j];
    #pragma unroll
    for (int i = 0; i < 8; i++) {
        float* o = g_hh + (mbase + m0 + i) * 256 + n0;
        #pragma unroll
        for (int j = 0; j < 8; j++) o[j] = fmaxf(acc[i][j] + bb[j], 0.f);
    }
}

// ============================================================================
// Kernel C: hr = [hh | f] @ [W2 ; Wres] + b2 + bres    M=65536, K=676, N=64
// ============================================================================
__global__ __launch_bounds__(256) void kC(const float* __restrict__ W2,
                                          const float* __restrict__ b2,
                                          const float* __restrict__ Wres,
                                          const float* __restrict__ bres)
{
    __shared__ float As[128][27];
    __shared__ __align__(16) float Bs[26][64];
    const int tid = threadIdx.x;
    const int m0 = (tid >> 4) * 8;
    const int n0 = (tid & 15) * 4;
    const size_t mbase = (size_t)blockIdx.x * 128;
    float acc[8][4] = {};

    for (int k0 = 0; k0 < 676; k0 += 26) {
        for (int idx = tid; idx < 128 * 26; idx += 256) {
            int m = idx / 26, kk = idx - m * 26;
            int k = k0 + kk;
            As[m][kk] = (k < 256) ? g_hh[(mbase + m) * 256 + k]
                                  : g_f [(mbase + m) * 420 + (k - 256)];
        }
        for (int idx = tid; idx < 26 * 64; idx += 256) {
            int r = idx / 64, c = idx - r * 64;
            int k = k0 + r;
            Bs[r][c] = (k < 256) ? W2[(size_t)k * 64 + c]
                                 : Wres[(size_t)(k - 256) * 64 + c];
        }
        __syncthreads();
        #pragma unroll
        for (int kk = 0; kk < 26; kk++) {
            float a[8];
            #pragma unroll
            for (int i = 0; i < 8; i++) a[i] = As[m0 + i][kk];
            float4 b4 = *reinterpret_cast<const float4*>(&Bs[kk][n0]);
            float b[4] = {b4.x, b4.y, b4.z, b4.w};
            #pragma unroll
            for (int i = 0; i < 8; i++)
                #pragma unroll
                for (int j = 0; j < 4; j++) acc[i][j] += a[i] * b[j];
        }
        __syncthreads();
    }
    float bb[4];
    #pragma unroll
    for (int j = 0; j < 4; j++) bb[j] = b2[n0 + j] + bres[n0 + j];
    #pragma unroll
    for (int i = 0; i < 8; i++) {
        float* o = g_hr + (mbase + m0 + i) * 64 + n0;
        #pragma unroll
        for (int j = 0; j < 4; j++) o[j] = acc[i][j] + bb[j];
    }
}

// ============================================================================
// Kernel D: out = LN64(hr) @ W3 + b3   (one warp per sample)
// ============================================================================
__global__ __launch_bounds__(256) void kD(const float* __restrict__ g_ln,
                                          const float* __restrict__ b_ln,
                                          const float* __restrict__ W3,
                                          const float* __restrict__ b3,
                                          float* __restrict__ out)
{
    int w = threadIdx.x >> 5, lane = threadIdx.x & 31;
    size_t s = (size_t)blockIdx.x * 8 + w;
    const float* r = g_hr + s * 64;
    float v0 = r[lane], v1 = r[lane + 32];
    float sum = v0 + v1, sq = v0 * v0 + v1 * v1;
    #pragma unroll
    for (int o = 16; o; o >>= 1) {
        sum += __shfl_xor_sync(FULL, sum, o);
        sq  += __shfl_xor_sync(FULL, sq,  o);
    }
    float m = sum * (1.f / 64.f);
    float var = sq * (1.f / 64.f) - m * m;
    float inv = rsqrtf(var + 1e-5f);
    float y0 = (v0 - m) * inv * g_ln[lane]      + b_ln[lane];
    float y1 = (v1 - m) * inv * g_ln[lane + 32] + b_ln[lane + 32];
    float d = y0 * W3[lane] + y1 * W3[lane + 32];
    #pragma unroll
    for (int o = 16; o; o >>= 1) d += __shfl_xor_sync(FULL, d, o);
    if (lane == 0) out[s] = d + b3[0];
}

// ============================================================================
extern "C" void kernel_launch(void* const* d_in, const int* in_sizes, int n_in,
                              void* d_out, int out_size)
{
    (void)in_sizes; (void)n_in; (void)out_size;
    const float* x = (const float*)d_in[0];

    kA<<<BATCH / 8, 256>>>(x,
        (const float*)d_in[1],  (const float*)d_in[2],
        (const float*)d_in[3],  (const float*)d_in[4],
        (const float*)d_in[5],  (const float*)d_in[6],
        (const float*)d_in[7],  (const float*)d_in[8],
        (const float*)d_in[9],  (const float*)d_in[10],
        (const float*)d_in[11], (const float*)d_in[12],
        (const float*)d_in[13], (const float*)d_in[14],
        (const float*)d_in[15], (const float*)d_in[16],
        (const float*)d_in[17]);

    kB<<<BATCH / 64, 256>>>((const float*)d_in[18], (const float*)d_in[19]);

    kC<<<BATCH / 128, 256>>>((const float*)d_in[20], (const float*)d_in[21],
                             (const float*)d_in[22], (const float*)d_in[23]);

    kD<<<BATCH / 8, 256>>>((const float*)d_in[24], (const float*)d_in[25],
                           (const float*)d_in[26], (const float*)d_in[27],
                           (float*)d_out);
}